// round 8
// baseline (speedup 1.0000x reference)
#include <cuda_runtime.h>

#define CC   48
#define B_   2
#define HH   64
#define WW   64
#define N_G  4096
#define N_P  1024
#define EPSF 1e-5f

// ---------------- scratch (static device globals; no allocation) ----------------
__device__ __align__(16) float g_f[4][B_*CC*N_G];        // global projections fa,fb,fc,fd
__device__ __align__(16) float g_mx[8*N_G];              // row max of (-E), global combos
__device__ __align__(16) float g_sm[8*N_G];              // row sum of exp,  global combos
__device__ __align__(16) float g_cat[B_*4*CC*N_G];       // concat of 4 global attn outputs
__device__ __align__(16) float g_outpre[B_*CC*N_G];      // input + gamma_all*atten (+ patches)
__device__ __align__(16) float g_pf[4][9*B_*CC*N_P];     // patch projections
__device__ __align__(16) float g_pmx[72*N_P];
__device__ __align__(16) float g_psm[72*N_P];
__device__ __align__(16) float g_pcat[9*B_*4*CC*N_P];
__device__ __align__(16) float g_pout[9*B_*CC*N_P];      // processed patch outputs

// ============ merged projection kernel ============
// bid < 128 : global. which = bid>>5, b = (bid>>4)&1, chunk = bid&15  (4*2*16 = 128)
// bid >= 128: patch.  q = bid-128; z = q>>3 (p*4+which), b = (q>>2)&1, chunk = q&3 (36*2*4 = 288)
__global__ void k_proj_all(const float* __restrict__ x0, const float* __restrict__ x1,
                           const float* __restrict__ x2, const float* __restrict__ x3,
                           const float* __restrict__ w0, const float* __restrict__ w1,
                           const float* __restrict__ w2, const float* __restrict__ w3,
                           const float* __restrict__ pw0, const float* __restrict__ pw1,
                           const float* __restrict__ pw2, const float* __restrict__ pw3)
{
    __shared__ float Ws[CC*CC];
    int bid = blockIdx.x, t = threadIdx.x;
    if (bid < 128) {
        int which = bid >> 5, b = (bid >> 4) & 1, chunk = bid & 15;
        const float* X = (which==0)?x0:(which==1)?x1:(which==2)?x2:x3;
        const float* W = (which==0)?w0:(which==1)?w1:(which==2)?w2:w3;
        for (int i = t; i < CC*CC; i += 256) Ws[i] = W[i];
        __syncthreads();
        int n = chunk*256 + t;
        float xr[CC];
        #pragma unroll
        for (int c = 0; c < CC; c++) xr[c] = X[(b*CC + c)*N_G + n];
        float* out = g_f[which] + b*CC*N_G;
        #pragma unroll 4
        for (int d = 0; d < CC; d++) {
            float a = 0.f;
            #pragma unroll
            for (int c = 0; c < CC; c++) a = fmaf(Ws[d*CC + c], xr[c], a);
            out[d*N_G + n] = a;
        }
    } else {
        int q = bid - 128;
        int z = q >> 3, b = (q >> 2) & 1, chunk = q & 3;
        int p = z >> 2, which = z & 3;
        const float* X = (which==0)?x0:(which==1)?x1:(which==2)?x2:x3;
        const float* W = ((which==0)?pw0:(which==1)?pw1:(which==2)?pw2:pw3) + p*CC*CC;
        for (int i = t; i < CC*CC; i += 256) Ws[i] = W[i];
        __syncthreads();
        int np  = chunk*256 + t;
        int r0  = (p/3)*16, c0 = (p%3)*16;
        int row = np >> 5, col = np & 31;
        int sp  = (r0 + row)*WW + c0 + col;
        float xr[CC];
        #pragma unroll
        for (int c = 0; c < CC; c++) xr[c] = X[(b*CC + c)*N_G + sp];
        float* out = g_pf[which] + (p*B_ + b)*CC*N_P;
        #pragma unroll 4
        for (int d = 0; d < CC; d++) {
            float a = 0.f;
            #pragma unroll
            for (int c = 0; c < CC; c++) a = fmaf(Ws[d*CC + c], xr[c], a);
            out[d*N_P + np] = a;
        }
    }
}

// ---------------- pass 1 body: row stats of softmax(-QtK) ----------------
// block (16,8) = 128 threads; tile = 64 n-rows (index passed in); loops over m-tiles of 64.
__device__ __forceinline__ void rowstats_body(const float* __restrict__ Q,
                                              const float* __restrict__ K,
                                              float* __restrict__ MX, float* __restrict__ SM,
                                              int N, int tile)
{
    __shared__ __align__(16) float Qs[CC*64];
    __shared__ __align__(16) float Ks[CC*64];
    int tx = threadIdx.x, ty = threadIdx.y;
    int t  = ty*16 + tx;
    int n0 = tile*64;

    for (int i = t; i < CC*64; i += 128) {
        int c = i >> 6, j = i & 63;
        Qs[i] = Q[c*N + n0 + j];
    }
    float mx[8], sm[8];
    #pragma unroll
    for (int i = 0; i < 8; i++) { mx[i] = -1e30f; sm[i] = 0.f; }

    int mtiles = N >> 6;
    for (int mt = 0; mt < mtiles; mt++) {
        __syncthreads();
        for (int i = t; i < CC*64; i += 128) {
            int c = i >> 6, j = i & 63;
            Ks[i] = K[c*N + (mt<<6) + j];
        }
        __syncthreads();
        float e[8][4];
        #pragma unroll
        for (int i = 0; i < 8; i++)
            #pragma unroll
            for (int j = 0; j < 4; j++) e[i][j] = 0.f;
        #pragma unroll
        for (int c = 0; c < CC; c++) {
            float4 qa = *(const float4*)&Qs[c*64 + ty*8];
            float4 qb = *(const float4*)&Qs[c*64 + ty*8 + 4];
            float4 k4 = *(const float4*)&Ks[c*64 + tx*4];
            float qq[8] = {qa.x, qa.y, qa.z, qa.w, qb.x, qb.y, qb.z, qb.w};
            float kk[4] = {k4.x, k4.y, k4.z, k4.w};
            #pragma unroll
            for (int i = 0; i < 8; i++)
                #pragma unroll
                for (int j = 0; j < 4; j++) e[i][j] = fmaf(qq[i], kk[j], e[i][j]);
        }
        #pragma unroll
        for (int i = 0; i < 8; i++) {
            float v0 = -e[i][0], v1 = -e[i][1], v2 = -e[i][2], v3 = -e[i][3];
            float nm   = fmaxf(fmaxf(v0, v1), fmaxf(v2, v3));
            float newm = fmaxf(mx[i], nm);
            sm[i] = sm[i]*__expf(mx[i] - newm)
                  + __expf(v0 - newm) + __expf(v1 - newm)
                  + __expf(v2 - newm) + __expf(v3 - newm);
            mx[i] = newm;
        }
    }
    #pragma unroll
    for (int i = 0; i < 8; i++) {
        float m = mx[i], s = sm[i];
        #pragma unroll
        for (int off = 8; off; off >>= 1) {
            float om = __shfl_down_sync(0xffffffffu, m, off, 16);
            float os = __shfl_down_sync(0xffffffffu, s, off, 16);
            float nm = fmaxf(m, om);
            s = s*__expf(m - nm) + os*__expf(om - nm);
            m = nm;
        }
        if (tx == 0) { MX[n0 + ty*8 + i] = m; SM[n0 + ty*8 + i] = s; }
    }
}

// merged rowstats: bid<512 global (combo=bid>>6, tile=bid&63); else patch (q=bid-512, combo=q>>4, tile=q&15)
__global__ void __launch_bounds__(128, 8) k_rowstats_all()
{
    int bid = blockIdx.x;
    if (bid < 512) {
        int combo = bid >> 6, tile = bid & 63;
        int b = combo >> 2, pair = combo & 3;
        rowstats_body(g_f[0] + b*CC*N_G, g_f[pair] + b*CC*N_G,
                      g_mx + combo*N_G, g_sm + combo*N_G, N_G, tile);
    } else {
        int q = bid - 512;
        int combo = q >> 4, tile = q & 15;          // combo = p*8 + b*4 + pair
        int p = combo >> 3, b = (combo >> 2) & 1, pair = combo & 3;
        rowstats_body(g_pf[0] + (p*B_ + b)*CC*N_P, g_pf[pair] + (p*B_ + b)*CC*N_P,
                      g_pmx + combo*N_P, g_psm + combo*N_P, N_P, tile);
    }
}

// ---------------- pass 2 body: O[c][m] = sum_n V[c][n] * exp(-E[n][m]-mx_n)/s_n ----------------
__device__ __forceinline__ void attn_out_body(const float* __restrict__ Q,
                                              const float* __restrict__ K,
                                              const float* __restrict__ V,
                                              const float* __restrict__ MX,
                                              const float* __restrict__ SM,
                                              float* __restrict__ Out, int N, int tile)
{
    __shared__ __align__(16) float Ks[CC*64];     // K tile for this block's m-columns (persistent)
    __shared__ __align__(16) float uQA[64*64];    // union: Q tile (CC*64) then A tile (64*64)
    __shared__ __align__(16) float Vs[CC*65];     // padded: conflict-free row reads
    __shared__ float mxs[64], rinv[64];

    int tx = threadIdx.x, ty = threadIdx.y;
    int t  = ty*16 + tx;
    int m0 = tile*64;

    for (int i = t; i < CC*64; i += 128) {
        int c = i >> 6, j = i & 63;
        Ks[i] = K[c*N + m0 + j];
    }
    float o[6][4];
    #pragma unroll
    for (int cc = 0; cc < 6; cc++)
        #pragma unroll
        for (int j = 0; j < 4; j++) o[cc][j] = 0.f;

    int ntiles = N >> 6;
    for (int nt = 0; nt < ntiles; nt++) {
        int n0 = nt << 6;
        __syncthreads();
        for (int i = t; i < CC*64; i += 128) {
            int c = i >> 6, j = i & 63;
            uQA[i]       = Q[c*N + n0 + j];
            Vs[c*65 + j] = V[c*N + n0 + j];
        }
        if (t < 64) { mxs[t] = MX[n0 + t]; rinv[t] = 1.0f / SM[n0 + t]; }
        __syncthreads();

        float e[8][4];
        #pragma unroll
        for (int i = 0; i < 8; i++)
            #pragma unroll
            for (int j = 0; j < 4; j++) e[i][j] = 0.f;
        #pragma unroll
        for (int c = 0; c < CC; c++) {
            float4 qa = *(const float4*)&uQA[c*64 + ty*8];
            float4 qb = *(const float4*)&uQA[c*64 + ty*8 + 4];
            float4 k4 = *(const float4*)&Ks[c*64 + tx*4];
            float qq[8] = {qa.x, qa.y, qa.z, qa.w, qb.x, qb.y, qb.z, qb.w};
            float kk[4] = {k4.x, k4.y, k4.z, k4.w};
            #pragma unroll
            for (int i = 0; i < 8; i++)
                #pragma unroll
                for (int j = 0; j < 4; j++) e[i][j] = fmaf(qq[i], kk[j], e[i][j]);
        }
        #pragma unroll
        for (int i = 0; i < 8; i++) {
            float mxn = mxs[ty*8 + i], rv = rinv[ty*8 + i];
            #pragma unroll
            for (int j = 0; j < 4; j++)
                e[i][j] = __expf(-e[i][j] - mxn) * rv;     // e now holds a[n][m]
        }
        __syncthreads();
        #pragma unroll
        for (int i = 0; i < 8; i++)
            *(float4*)&uQA[(ty*8 + i)*64 + tx*4] =
                make_float4(e[i][0], e[i][1], e[i][2], e[i][3]);
        __syncthreads();

        #pragma unroll 4
        for (int nn = 0; nn < 64; nn++) {
            float4 av = *(const float4*)&uQA[nn*64 + tx*4];
            float aj[4] = {av.x, av.y, av.z, av.w};
            float vv[6];
            #pragma unroll
            for (int cc = 0; cc < 6; cc++) vv[cc] = Vs[(ty*6 + cc)*65 + nn];
            #pragma unroll
            for (int cc = 0; cc < 6; cc++)
                #pragma unroll
                for (int j = 0; j < 4; j++)
                    o[cc][j] = fmaf(vv[cc], aj[j], o[cc][j]);
        }
    }
    #pragma unroll
    for (int cc = 0; cc < 6; cc++)
        *(float4*)&Out[(ty*6 + cc)*N + m0 + tx*4] =
            make_float4(o[cc][0], o[cc][1], o[cc][2], o[cc][3]);
}

// merged attn: same decode as rowstats
__global__ void __launch_bounds__(128, 8) k_attn_all()
{
    int bid = blockIdx.x;
    if (bid < 512) {
        int combo = bid >> 6, tile = bid & 63;
        int b = combo >> 2, pair = combo & 3;
        const float* kv = g_f[pair] + b*CC*N_G;
        attn_out_body(g_f[0] + b*CC*N_G, kv, kv,
                      g_mx + combo*N_G, g_sm + combo*N_G,
                      g_cat + (b*4*CC + pair*CC)*N_G, N_G, tile);
    } else {
        int q = bid - 512;
        int combo = q >> 4, tile = q & 15;
        int p = combo >> 3, b = (combo >> 2) & 1, pair = combo & 3;
        const float* kv = g_pf[pair] + (p*B_ + b)*CC*N_P;
        attn_out_body(g_pf[0] + (p*B_ + b)*CC*N_P, kv, kv,
                      g_pmx + combo*N_P, g_psm + combo*N_P,
                      g_pcat + ((p*B_ + b)*4*CC + pair*CC)*N_P, N_P, tile);
    }
}

// ============ merged fuse kernel ============
// bid < 32 : global (b = bid>>4, chunk = bid&15), out_pre = inp + gamma*relu(BN(Linear))
// bid >= 32: patch  (q = bid-32; p = q>>3, b = (q>>2)&1, chunk = q&3), 0.5*gamma_p*relu(BN(Linear))
__global__ void k_fuse_all(const float* __restrict__ inp,
                           const float* __restrict__ fw, const float* __restrict__ fb,
                           const float* __restrict__ fg, const float* __restrict__ fbb,
                           const float* __restrict__ fm, const float* __restrict__ fv,
                           const float* __restrict__ gamma_all,
                           const float* __restrict__ Pw, const float* __restrict__ Pb,
                           const float* __restrict__ Pg, const float* __restrict__ Pbb,
                           const float* __restrict__ Pm, const float* __restrict__ Pv,
                           const float* __restrict__ gp)
{
    __shared__ float Ws[CC*4*CC];
    int bid = blockIdx.x, t = threadIdx.x;
    if (bid < 32) {
        int b = bid >> 4, chunk = bid & 15;
        for (int i = t; i < CC*192; i += 256) Ws[i] = fw[i];
        __syncthreads();
        int n = chunk*256 + t;
        float acc[CC];
        #pragma unroll
        for (int o = 0; o < CC; o++) acc[o] = 0.f;
        const float* cat = g_cat + b*4*CC*N_G;
        for (int j = 0; j < 4*CC; j++) {
            float x = cat[j*N_G + n];
            #pragma unroll
            for (int o = 0; o < CC; o++) acc[o] = fmaf(Ws[o*192 + j], x, acc[o]);
        }
        float ga = gamma_all[0];
        #pragma unroll 4
        for (int o = 0; o < CC; o++) {
            float y = acc[o] + fb[o];
            y = (y - fm[o]) * (fg[o] * rsqrtf(fv[o] + EPSF)) + fbb[o];
            y = fmaxf(y, 0.f);
            g_outpre[(b*CC + o)*N_G + n] = inp[(b*CC + o)*N_G + n] + ga*y;
        }
    } else {
        int q = bid - 32;
        int p = q >> 3, b = (q >> 2) & 1, chunk = q & 3;
        const float* w = Pw + p*CC*192;
        for (int i = t; i < CC*192; i += 256) Ws[i] = w[i];
        __syncthreads();
        int n = chunk*256 + t;
        float acc[CC];
        #pragma unroll
        for (int o = 0; o < CC; o++) acc[o] = 0.f;
        const float* cat = g_pcat + (p*B_ + b)*4*CC*N_P;
        for (int j = 0; j < 4*CC; j++) {
            float x = cat[j*N_P + n];
            #pragma unroll
            for (int o = 0; o < CC; o++) acc[o] = fmaf(Ws[o*192 + j], x, acc[o]);
        }
        float gph = 0.5f * gp[p];
        #pragma unroll 4
        for (int o = 0; o < CC; o++) {
            float y = acc[o] + Pb[p*CC + o];
            y = (y - Pm[p*CC + o]) * (Pg[p*CC + o] * rsqrtf(Pv[p*CC + o] + EPSF)) + Pbb[p*CC + o];
            g_pout[((p*B_ + b)*CC + o)*N_P + n] = gph * fmaxf(y, 0.f);
        }
    }
}

// ---------------- combine: deterministic gather of overlapping patches ----------------
__global__ void k_combine()
{
    int i = blockIdx.x*256 + threadIdx.x;      // < B*C*N_G
    int n  = i & (N_G - 1);
    int bc = i >> 12;
    int c  = bc % CC, b = bc / CC;
    int h  = n >> 6, w = n & 63;
    float s = g_outpre[i];
    #pragma unroll
    for (int p = 0; p < 9; p++) {
        int dr = h - (p/3)*16, dc = w - (p%3)*16;
        if ((unsigned)dr < 32u && (unsigned)dc < 32u)
            s += g_pout[((p*B_ + b)*CC + c)*N_P + dr*32 + dc];
    }
    g_outpre[i] = s;
}

// ---------------- 3x3 conv (SAME) + bias + BN + ReLU -> d_out ----------------
__global__ void k_conv(const float* __restrict__ ow, const float* __restrict__ ob,
                       const float* __restrict__ og, const float* __restrict__ obb,
                       const float* __restrict__ om, const float* __restrict__ ov,
                       float* __restrict__ out)
{
    __shared__ float tile[18*18];
    __shared__ float wsm[CC*9];
    int b  = blockIdx.y;
    int th = (blockIdx.x >> 2) * 16, tw = (blockIdx.x & 3) * 16;
    int t  = threadIdx.x;
    int hh = t >> 4, ww = t & 15;
    float acc[CC];
    #pragma unroll
    for (int o = 0; o < CC; o++) acc[o] = 0.f;

    for (int c = 0; c < CC; c++) {
        __syncthreads();
        for (int i = t; i < 324; i += 256) {
            int r = i / 18, cl = i % 18;
            int h = th + r - 1, w = tw + cl - 1;
            tile[i] = (h >= 0 && h < HH && w >= 0 && w < WW)
                    ? g_outpre[((b*CC + c) << 12) + (h << 6) + w] : 0.f;
        }
        for (int i = t; i < CC*9; i += 256)
            wsm[i] = ow[(i/9)*CC*9 + c*9 + (i%9)];
        __syncthreads();
        float in9[9];
        #pragma unroll
        for (int kh = 0; kh < 3; kh++)
            #pragma unroll
            for (int kw = 0; kw < 3; kw++)
                in9[kh*3 + kw] = tile[(hh + kh)*18 + ww + kw];
        #pragma unroll 8
        for (int o = 0; o < CC; o++) {
            float a = acc[o];
            #pragma unroll
            for (int k = 0; k < 9; k++) a = fmaf(wsm[o*9 + k], in9[k], a);
            acc[o] = a;
        }
    }
    int hw = ((th + hh) << 6) + tw + ww;
    #pragma unroll 4
    for (int o = 0; o < CC; o++) {
        float z = acc[o] + ob[o];
        z = (z - om[o]) * (og[o] * rsqrtf(ov[o] + EPSF)) + obb[o];
        out[((b*CC + o) << 12) + hw] = fmaxf(z, 0.f);
    }
}

// ---------------- launcher ----------------
extern "C" void kernel_launch(void* const* d_in, const int* in_sizes, int n_in,
                              void* d_out, int out_size)
{
    const float* inp     = (const float*)d_in[0];
    const float* featb   = (const float*)d_in[1];
    const float* featc   = (const float*)d_in[2];
    const float* featd   = (const float*)d_in[3];
    const float* Wfa_all = (const float*)d_in[4];
    const float* Wfb_all = (const float*)d_in[5];
    const float* Wfc_all = (const float*)d_in[6];
    const float* Wfd_all = (const float*)d_in[7];
    const float* Wfa     = (const float*)d_in[8];
    const float* Wfb     = (const float*)d_in[9];
    const float* Wfc     = (const float*)d_in[10];
    const float* Wfd     = (const float*)d_in[11];
    const float* fuse_w  = (const float*)d_in[12];
    const float* fuse_b  = (const float*)d_in[13];
    const float* fuse_g  = (const float*)d_in[14];
    const float* fuse_bb = (const float*)d_in[15];
    const float* fuse_m  = (const float*)d_in[16];
    const float* fuse_v  = (const float*)d_in[17];
    const float* fuseP_w = (const float*)d_in[18];
    const float* fuseP_b = (const float*)d_in[19];
    const float* fuseP_g = (const float*)d_in[20];
    const float* fuseP_bb= (const float*)d_in[21];
    const float* fuseP_m = (const float*)d_in[22];
    const float* fuseP_v = (const float*)d_in[23];
    const float* gamma_a = (const float*)d_in[24];
    const float* gamma_p = (const float*)d_in[25];
    const float* out_w   = (const float*)d_in[26];
    const float* out_b   = (const float*)d_in[27];
    const float* out_g   = (const float*)d_in[28];
    const float* out_bb  = (const float*)d_in[29];
    const float* out_m   = (const float*)d_in[30];
    const float* out_v   = (const float*)d_in[31];

    k_proj_all    <<<416, 256>>>(inp, featb, featc, featd,
                                 Wfa_all, Wfb_all, Wfc_all, Wfd_all,
                                 Wfa, Wfb, Wfc, Wfd);
    k_rowstats_all<<<1664, dim3(16,8)>>>();
    k_attn_all    <<<1664, dim3(16,8)>>>();
    k_fuse_all    <<<104, 256>>>(inp, fuse_w, fuse_b, fuse_g, fuse_bb, fuse_m, fuse_v, gamma_a,
                                 fuseP_w, fuseP_b, fuseP_g, fuseP_bb, fuseP_m, fuseP_v, gamma_p);
    k_combine     <<<(B_*CC*N_G)/256, 256>>>();
    k_conv        <<<dim3(16, B_), 256>>>(out_w, out_b, out_g, out_bb, out_m, out_v,
                                          (float*)d_out);
}

// round 14
// speedup vs baseline: 1.2312x; 1.2312x over previous
#include <cuda_runtime.h>

#define CC   48
#define B_   2
#define HH   64
#define WW   64
#define N_G  4096
#define N_P  1024
#define EPSF 1e-5f

typedef unsigned long long u64c;

// ---- packed fp32x2 helpers (sm_100+; bit-exact dual fp32 lanes) ----
__device__ __forceinline__ u64c pack2(float lo, float hi) {
    u64c r; asm("mov.b64 %0, {%1, %2};" : "=l"(r) : "f"(lo), "f"(hi)); return r;
}
__device__ __forceinline__ void unpack2(u64c v, float& lo, float& hi) {
    asm("mov.b64 {%0, %1}, %2;" : "=f"(lo), "=f"(hi) : "l"(v));
}
__device__ __forceinline__ u64c fma2(u64c a, u64c b, u64c c) {
    u64c d; asm("fma.rn.f32x2 %0, %1, %2, %3;" : "=l"(d) : "l"(a), "l"(b), "l"(c)); return d;
}

// ---------------- scratch (static device globals; no allocation) ----------------
__device__ __align__(16) float g_f[4][B_*CC*N_G];
__device__ __align__(16) float g_mx[8*N_G];
__device__ __align__(16) float g_sm[8*N_G];
__device__ __align__(16) float g_cat[B_*4*CC*N_G];
__device__ __align__(16) float g_outpre[B_*CC*N_G];
__device__ __align__(16) float g_pf[4][9*B_*CC*N_P];
__device__ __align__(16) float g_pmx[72*N_P];
__device__ __align__(16) float g_psm[72*N_P];
__device__ __align__(16) float g_pcat[9*B_*4*CC*N_P];
__device__ __align__(16) float g_pout[9*B_*CC*N_P];

// ============ merged projection kernel ============
__global__ void k_proj_all(const float* __restrict__ x0, const float* __restrict__ x1,
                           const float* __restrict__ x2, const float* __restrict__ x3,
                           const float* __restrict__ w0, const float* __restrict__ w1,
                           const float* __restrict__ w2, const float* __restrict__ w3,
                           const float* __restrict__ pw0, const float* __restrict__ pw1,
                           const float* __restrict__ pw2, const float* __restrict__ pw3)
{
    __shared__ float Ws[CC*CC];
    int bid = blockIdx.x, t = threadIdx.x;
    if (bid < 128) {
        int which = bid >> 5, b = (bid >> 4) & 1, chunk = bid & 15;
        const float* X = (which==0)?x0:(which==1)?x1:(which==2)?x2:x3;
        const float* W = (which==0)?w0:(which==1)?w1:(which==2)?w2:w3;
        for (int i = t; i < CC*CC; i += 256) Ws[i] = W[i];
        __syncthreads();
        int n = chunk*256 + t;
        float xr[CC];
        #pragma unroll
        for (int c = 0; c < CC; c++) xr[c] = X[(b*CC + c)*N_G + n];
        float* out = g_f[which] + b*CC*N_G;
        #pragma unroll 4
        for (int d = 0; d < CC; d++) {
            float a = 0.f;
            #pragma unroll
            for (int c = 0; c < CC; c++) a = fmaf(Ws[d*CC + c], xr[c], a);
            out[d*N_G + n] = a;
        }
    } else {
        int q = bid - 128;
        int z = q >> 3, b = (q >> 2) & 1, chunk = q & 3;
        int p = z >> 2, which = z & 3;
        const float* X = (which==0)?x0:(which==1)?x1:(which==2)?x2:x3;
        const float* W = ((which==0)?pw0:(which==1)?pw1:(which==2)?pw2:pw3) + p*CC*CC;
        for (int i = t; i < CC*CC; i += 256) Ws[i] = W[i];
        __syncthreads();
        int np  = chunk*256 + t;
        int r0  = (p/3)*16, c0 = (p%3)*16;
        int row = np >> 5, col = np & 31;
        int sp  = (r0 + row)*WW + c0 + col;
        float xr[CC];
        #pragma unroll
        for (int c = 0; c < CC; c++) xr[c] = X[(b*CC + c)*N_G + sp];
        float* out = g_pf[which] + (p*B_ + b)*CC*N_P;
        #pragma unroll 4
        for (int d = 0; d < CC; d++) {
            float a = 0.f;
            #pragma unroll
            for (int c = 0; c < CC; c++) a = fmaf(Ws[d*CC + c], xr[c], a);
            out[d*N_P + np] = a;
        }
    }
}

// ---------------- pass 1 body: row stats of softmax(-QtK), FMA2 E-loop ----------------
__device__ __forceinline__ void rowstats_body(const float* __restrict__ Q,
                                              const float* __restrict__ K,
                                              float* __restrict__ MX, float* __restrict__ SM,
                                              int N, int tile)
{
    __shared__ __align__(16) float Qs[CC*64];
    __shared__ __align__(16) float Ks[CC*64];
    int tx = threadIdx.x, ty = threadIdx.y;
    int t  = ty*16 + tx;
    int n0 = tile*64;

    for (int i = t; i < CC*64; i += 128) {
        int c = i >> 6, j = i & 63;
        Qs[i] = Q[c*N + n0 + j];
    }
    float mx[8], sm[8];
    #pragma unroll
    for (int i = 0; i < 8; i++) { mx[i] = -1e30f; sm[i] = 0.f; }

    int mtiles = N >> 6;
    for (int mt = 0; mt < mtiles; mt++) {
        __syncthreads();
        for (int i = t; i < CC*64; i += 128) {
            int c = i >> 6, j = i & 63;
            Ks[i] = K[c*N + (mt<<6) + j];
        }
        __syncthreads();
        // E tile: rows paired in fp32x2 lanes (lo=row 2ii, hi=row 2ii+1)
        u64c e2[4][4];
        #pragma unroll
        for (int ii = 0; ii < 4; ii++)
            #pragma unroll
            for (int j = 0; j < 4; j++) e2[ii][j] = 0ull;
        #pragma unroll
        for (int c = 0; c < CC; c++) {
            u64c q2[4];
            #pragma unroll
            for (int ii = 0; ii < 4; ii++)
                q2[ii] = *(const u64c*)&Qs[c*64 + ty*8 + 2*ii];
            float4 k4 = *(const float4*)&Ks[c*64 + tx*4];
            u64c k2[4] = {pack2(k4.x,k4.x), pack2(k4.y,k4.y),
                          pack2(k4.z,k4.z), pack2(k4.w,k4.w)};
            #pragma unroll
            for (int ii = 0; ii < 4; ii++)
                #pragma unroll
                for (int j = 0; j < 4; j++)
                    e2[ii][j] = fma2(q2[ii], k2[j], e2[ii][j]);
        }
        float e[8][4];
        #pragma unroll
        for (int ii = 0; ii < 4; ii++)
            #pragma unroll
            for (int j = 0; j < 4; j++)
                unpack2(e2[ii][j], e[2*ii][j], e[2*ii+1][j]);
        #pragma unroll
        for (int i = 0; i < 8; i++) {
            float v0 = -e[i][0], v1 = -e[i][1], v2 = -e[i][2], v3 = -e[i][3];
            float nm   = fmaxf(fmaxf(v0, v1), fmaxf(v2, v3));
            float newm = fmaxf(mx[i], nm);
            sm[i] = sm[i]*__expf(mx[i] - newm)
                  + __expf(v0 - newm) + __expf(v1 - newm)
                  + __expf(v2 - newm) + __expf(v3 - newm);
            mx[i] = newm;
        }
    }
    #pragma unroll
    for (int i = 0; i < 8; i++) {
        float m = mx[i], s = sm[i];
        #pragma unroll
        for (int off = 8; off; off >>= 1) {
            float om = __shfl_down_sync(0xffffffffu, m, off, 16);
            float os = __shfl_down_sync(0xffffffffu, s, off, 16);
            float nm = fmaxf(m, om);
            s = s*__expf(m - nm) + os*__expf(om - nm);
            m = nm;
        }
        if (tx == 0) { MX[n0 + ty*8 + i] = m; SM[n0 + ty*8 + i] = s; }
    }
}

__global__ void __launch_bounds__(128, 6) k_rowstats_all()
{
    int bid = blockIdx.x;
    if (bid < 512) {
        int combo = bid >> 6, tile = bid & 63;
        int b = combo >> 2, pair = combo & 3;
        rowstats_body(g_f[0] + b*CC*N_G, g_f[pair] + b*CC*N_G,
                      g_mx + combo*N_G, g_sm + combo*N_G, N_G, tile);
    } else {
        int q = bid - 512;
        int combo = q >> 4, tile = q & 15;
        int p = combo >> 3, b = (combo >> 2) & 1, pair = combo & 3;
        rowstats_body(g_pf[0] + (p*B_ + b)*CC*N_P, g_pf[pair] + (p*B_ + b)*CC*N_P,
                      g_pmx + combo*N_P, g_psm + combo*N_P, N_P, tile);
    }
}

// ---------------- pass 2 body: FMA2 E recompute + FMA2 V.A with channel-paired Vs2 ----------------
__device__ __forceinline__ void attn_out_body(const float* __restrict__ Q,
                                              const float* __restrict__ K,
                                              const float* __restrict__ V,
                                              const float* __restrict__ MX,
                                              const float* __restrict__ SM,
                                              float* __restrict__ Out, int N, int tile)
{
    __shared__ __align__(16) float Ks[CC*64];     // 12.3 KB
    __shared__ __align__(16) float uQA[64*64];    // 16.4 KB (union: Q tile then A tile)
    __shared__ __align__(16) u64c  Vs2[24*65];    // 12.5 KB, channel pairs (2c2, 2c2+1)
    __shared__ float mxs[64], rinv[64];

    int tx = threadIdx.x, ty = threadIdx.y;
    int t  = ty*16 + tx;
    int m0 = tile*64;

    for (int i = t; i < CC*64; i += 128) {
        int c = i >> 6, j = i & 63;
        Ks[i] = K[c*N + m0 + j];
    }
    u64c o2[3][4];   // lanes: (channel ty*6+2ccc, ty*6+2ccc+1)
    #pragma unroll
    for (int ccc = 0; ccc < 3; ccc++)
        #pragma unroll
        for (int j = 0; j < 4; j++) o2[ccc][j] = 0ull;

    int ntiles = N >> 6;
    for (int nt = 0; nt < ntiles; nt++) {
        int n0 = nt << 6;
        __syncthreads();
        for (int i = t; i < CC*64; i += 128) {
            int c = i >> 6, j = i & 63;
            uQA[i] = Q[c*N + n0 + j];
        }
        for (int i = t; i < 24*64; i += 128) {
            int c2 = i >> 6, j = i & 63;
            Vs2[c2*65 + j] = pack2(V[(2*c2)*N + n0 + j], V[(2*c2+1)*N + n0 + j]);
        }
        if (t < 64) { mxs[t] = MX[n0 + t]; rinv[t] = 1.0f / SM[n0 + t]; }
        __syncthreads();

        u64c e2[4][4];
        #pragma unroll
        for (int ii = 0; ii < 4; ii++)
            #pragma unroll
            for (int j = 0; j < 4; j++) e2[ii][j] = 0ull;
        #pragma unroll
        for (int c = 0; c < CC; c++) {
            u64c q2[4];
            #pragma unroll
            for (int ii = 0; ii < 4; ii++)
                q2[ii] = *(const u64c*)&uQA[c*64 + ty*8 + 2*ii];
            float4 k4 = *(const float4*)&Ks[c*64 + tx*4];
            u64c k2[4] = {pack2(k4.x,k4.x), pack2(k4.y,k4.y),
                          pack2(k4.z,k4.z), pack2(k4.w,k4.w)};
            #pragma unroll
            for (int ii = 0; ii < 4; ii++)
                #pragma unroll
                for (int j = 0; j < 4; j++)
                    e2[ii][j] = fma2(q2[ii], k2[j], e2[ii][j]);
        }
        float e[8][4];
        #pragma unroll
        for (int ii = 0; ii < 4; ii++)
            #pragma unroll
            for (int j = 0; j < 4; j++)
                unpack2(e2[ii][j], e[2*ii][j], e[2*ii+1][j]);
        #pragma unroll
        for (int i = 0; i < 8; i++) {
            float mxn = mxs[ty*8 + i], rv = rinv[ty*8 + i];
            #pragma unroll
            for (int j = 0; j < 4; j++)
                e[i][j] = __expf(-e[i][j] - mxn) * rv;
        }
        __syncthreads();
        #pragma unroll
        for (int i = 0; i < 8; i++)
            *(float4*)&uQA[(ty*8 + i)*64 + tx*4] =
                make_float4(e[i][0], e[i][1], e[i][2], e[i][3]);
        __syncthreads();

        #pragma unroll 4
        for (int nn = 0; nn < 64; nn++) {
            float4 av = *(const float4*)&uQA[nn*64 + tx*4];
            u64c a2[4] = {pack2(av.x,av.x), pack2(av.y,av.y),
                          pack2(av.z,av.z), pack2(av.w,av.w)};
            u64c v2[3];
            #pragma unroll
            for (int ccc = 0; ccc < 3; ccc++)
                v2[ccc] = Vs2[(ty*3 + ccc)*65 + nn];
            #pragma unroll
            for (int ccc = 0; ccc < 3; ccc++)
                #pragma unroll
                for (int j = 0; j < 4; j++)
                    o2[ccc][j] = fma2(v2[ccc], a2[j], o2[ccc][j]);
        }
    }
    #pragma unroll
    for (int ccc = 0; ccc < 3; ccc++) {
        float lo[4], hi[4];
        #pragma unroll
        for (int j = 0; j < 4; j++) unpack2(o2[ccc][j], lo[j], hi[j]);
        *(float4*)&Out[(ty*6 + 2*ccc)*N     + m0 + tx*4] = make_float4(lo[0], lo[1], lo[2], lo[3]);
        *(float4*)&Out[(ty*6 + 2*ccc + 1)*N + m0 + tx*4] = make_float4(hi[0], hi[1], hi[2], hi[3]);
    }
}

__global__ void __launch_bounds__(128, 5) k_attn_all()
{
    int bid = blockIdx.x;
    if (bid < 512) {
        int combo = bid >> 6, tile = bid & 63;
        int b = combo >> 2, pair = combo & 3;
        const float* kv = g_f[pair] + b*CC*N_G;
        attn_out_body(g_f[0] + b*CC*N_G, kv, kv,
                      g_mx + combo*N_G, g_sm + combo*N_G,
                      g_cat + (b*4*CC + pair*CC)*N_G, N_G, tile);
    } else {
        int q = bid - 512;
        int combo = q >> 4, tile = q & 15;
        int p = combo >> 3, b = (combo >> 2) & 1, pair = combo & 3;
        const float* kv = g_pf[pair] + (p*B_ + b)*CC*N_P;
        attn_out_body(g_pf[0] + (p*B_ + b)*CC*N_P, kv, kv,
                      g_pmx + combo*N_P, g_psm + combo*N_P,
                      g_pcat + ((p*B_ + b)*4*CC + pair*CC)*N_P, N_P, tile);
    }
}

// ============ merged fuse kernel, 4-way output split, transposed weight tile ============
// global: bid<128: b=bid>>6, chunk=(bid>>2)&15, oq=bid&3
// patch : q=bid-128: p=q>>5, r=q&31, b=r>>4, chunk=(r>>2)&3, oq=r&3   (total 416 blocks)
__global__ void k_fuse_all(const float* __restrict__ inp,
                           const float* __restrict__ fw, const float* __restrict__ fb,
                           const float* __restrict__ fg, const float* __restrict__ fbb,
                           const float* __restrict__ fm, const float* __restrict__ fv,
                           const float* __restrict__ gamma_all,
                           const float* __restrict__ Pw, const float* __restrict__ Pb,
                           const float* __restrict__ Pg, const float* __restrict__ Pbb,
                           const float* __restrict__ Pm, const float* __restrict__ Pv,
                           const float* __restrict__ gp)
{
    __shared__ __align__(16) float Wt[192*12];   // transposed: Wt[j*12+o]
    int bid = blockIdx.x, t = threadIdx.x;
    if (bid < 128) {
        int b = bid >> 6, chunk = (bid >> 2) & 15, oq = bid & 3;
        for (int i = t; i < 192*12; i += 256) {
            int o = i % 12, j = i / 12;
            Wt[j*12 + o] = fw[(oq*12 + o)*192 + j];
        }
        __syncthreads();
        int n = chunk*256 + t;
        float acc[12];
        #pragma unroll
        for (int o = 0; o < 12; o++) acc[o] = 0.f;
        const float* cat = g_cat + b*4*CC*N_G;
        for (int j = 0; j < 4*CC; j++) {
            float x = cat[j*N_G + n];
            float4 w0 = *(const float4*)&Wt[j*12];
            float4 w1 = *(const float4*)&Wt[j*12 + 4];
            float4 w2 = *(const float4*)&Wt[j*12 + 8];
            acc[0] = fmaf(w0.x, x, acc[0]);  acc[1] = fmaf(w0.y, x, acc[1]);
            acc[2] = fmaf(w0.z, x, acc[2]);  acc[3] = fmaf(w0.w, x, acc[3]);
            acc[4] = fmaf(w1.x, x, acc[4]);  acc[5] = fmaf(w1.y, x, acc[5]);
            acc[6] = fmaf(w1.z, x, acc[6]);  acc[7] = fmaf(w1.w, x, acc[7]);
            acc[8] = fmaf(w2.x, x, acc[8]);  acc[9] = fmaf(w2.y, x, acc[9]);
            acc[10] = fmaf(w2.z, x, acc[10]); acc[11] = fmaf(w2.w, x, acc[11]);
        }
        float ga = gamma_all[0];
        #pragma unroll
        for (int o = 0; o < 12; o++) {
            int og = oq*12 + o;
            float y = acc[o] + fb[og];
            y = (y - fm[og]) * (fg[og] * rsqrtf(fv[og] + EPSF)) + fbb[og];
            y = fmaxf(y, 0.f);
            g_outpre[(b*CC + og)*N_G + n] = inp[(b*CC + og)*N_G + n] + ga*y;
        }
    } else {
        int q = bid - 128;
        int p = q >> 5, r = q & 31;
        int b = r >> 4, chunk = (r >> 2) & 3, oq = r & 3;
        const float* w = Pw + p*CC*192;
        for (int i = t; i < 192*12; i += 256) {
            int o = i % 12, j = i / 12;
            Wt[j*12 + o] = w[(oq*12 + o)*192 + j];
        }
        __syncthreads();
        int n = chunk*256 + t;
        float acc[12];
        #pragma unroll
        for (int o = 0; o < 12; o++) acc[o] = 0.f;
        const float* cat = g_pcat + (p*B_ + b)*4*CC*N_P;
        for (int j = 0; j < 4*CC; j++) {
            float x = cat[j*N_P + n];
            float4 w0 = *(const float4*)&Wt[j*12];
            float4 w1 = *(const float4*)&Wt[j*12 + 4];
            float4 w2 = *(const float4*)&Wt[j*12 + 8];
            acc[0] = fmaf(w0.x, x, acc[0]);  acc[1] = fmaf(w0.y, x, acc[1]);
            acc[2] = fmaf(w0.z, x, acc[2]);  acc[3] = fmaf(w0.w, x, acc[3]);
            acc[4] = fmaf(w1.x, x, acc[4]);  acc[5] = fmaf(w1.y, x, acc[5]);
            acc[6] = fmaf(w1.z, x, acc[6]);  acc[7] = fmaf(w1.w, x, acc[7]);
            acc[8] = fmaf(w2.x, x, acc[8]);  acc[9] = fmaf(w2.y, x, acc[9]);
            acc[10] = fmaf(w2.z, x, acc[10]); acc[11] = fmaf(w2.w, x, acc[11]);
        }
        float gph = 0.5f * gp[p];
        #pragma unroll
        for (int o = 0; o < 12; o++) {
            int og = oq*12 + o;
            float y = acc[o] + Pb[p*CC + og];
            y = (y - Pm[p*CC + og]) * (Pg[p*CC + og] * rsqrtf(Pv[p*CC + og] + EPSF)) + Pbb[p*CC + og];
            g_pout[((p*B_ + b)*CC + og)*N_P + n] = gph * fmaxf(y, 0.f);
        }
    }
}

// ---------------- combine ----------------
__global__ void k_combine()
{
    int i = blockIdx.x*256 + threadIdx.x;
    int n  = i & (N_G - 1);
    int bc = i >> 12;
    int c  = bc % CC, b = bc / CC;
    int h  = n >> 6, w = n & 63;
    float s = g_outpre[i];
    #pragma unroll
    for (int p = 0; p < 9; p++) {
        int dr = h - (p/3)*16, dc = w - (p%3)*16;
        if ((unsigned)dr < 32u && (unsigned)dc < 32u)
            s += g_pout[((p*B_ + b)*CC + c)*N_P + dr*32 + dc];
    }
    g_outpre[i] = s;
}

// ---------------- 3x3 conv + bias + BN + ReLU ----------------
__global__ void k_conv(const float* __restrict__ ow, const float* __restrict__ ob,
                       const float* __restrict__ og, const float* __restrict__ obb,
                       const float* __restrict__ om, const float* __restrict__ ov,
                       float* __restrict__ out)
{
    __shared__ float tile[18*18];
    __shared__ float wsm[CC*9];
    int b  = blockIdx.y;
    int th = (blockIdx.x >> 2) * 16, tw = (blockIdx.x & 3) * 16;
    int t  = threadIdx.x;
    int hh = t >> 4, ww = t & 15;
    float acc[CC];
    #pragma unroll
    for (int o = 0; o < CC; o++) acc[o] = 0.f;

    for (int c = 0; c < CC; c++) {
        __syncthreads();
        for (int i = t; i < 324; i += 256) {
            int r = i / 18, cl = i % 18;
            int h = th + r - 1, w = tw + cl - 1;
            tile[i] = (h >= 0 && h < HH && w >= 0 && w < WW)
                    ? g_outpre[((b*CC + c) << 12) + (h << 6) + w] : 0.f;
        }
        for (int i = t; i < CC*9; i += 256)
            wsm[i] = ow[(i/9)*CC*9 + c*9 + (i%9)];
        __syncthreads();
        float in9[9];
        #pragma unroll
        for (int kh = 0; kh < 3; kh++)
            #pragma unroll
            for (int kw = 0; kw < 3; kw++)
                in9[kh*3 + kw] = tile[(hh + kh)*18 + ww + kw];
        #pragma unroll 8
        for (int o = 0; o < CC; o++) {
            float a = acc[o];
            #pragma unroll
            for (int k = 0; k < 9; k++) a = fmaf(wsm[o*9 + k], in9[k], a);
            acc[o] = a;
        }
    }
    int hw = ((th + hh) << 6) + tw + ww;
    #pragma unroll 4
    for (int o = 0; o < CC; o++) {
        float z = acc[o] + ob[o];
        z = (z - om[o]) * (og[o] * rsqrtf(ov[o] + EPSF)) + obb[o];
        out[((b*CC + o) << 12) + hw] = fmaxf(z, 0.f);
    }
}

// ---------------- launcher ----------------
extern "C" void kernel_launch(void* const* d_in, const int* in_sizes, int n_in,
                              void* d_out, int out_size)
{
    const float* inp     = (const float*)d_in[0];
    const float* featb   = (const float*)d_in[1];
    const float* featc   = (const float*)d_in[2];
    const float* featd   = (const float*)d_in[3];
    const float* Wfa_all = (const float*)d_in[4];
    const float* Wfb_all = (const float*)d_in[5];
    const float* Wfc_all = (const float*)d_in[6];
    const float* Wfd_all = (const float*)d_in[7];
    const float* Wfa     = (const float*)d_in[8];
    const float* Wfb     = (const float*)d_in[9];
    const float* Wfc     = (const float*)d_in[10];
    const float* Wfd     = (const float*)d_in[11];
    const float* fuse_w  = (const float*)d_in[12];
    const float* fuse_b  = (const float*)d_in[13];
    const float* fuse_g  = (const float*)d_in[14];
    const float* fuse_bb = (const float*)d_in[15];
    const float* fuse_m  = (const float*)d_in[16];
    const float* fuse_v  = (const float*)d_in[17];
    const float* fuseP_w = (const float*)d_in[18];
    const float* fuseP_b = (const float*)d_in[19];
    const float* fuseP_g = (const float*)d_in[20];
    const float* fuseP_bb= (const float*)d_in[21];
    const float* fuseP_m = (const float*)d_in[22];
    const float* fuseP_v = (const float*)d_in[23];
    const float* gamma_a = (const float*)d_in[24];
    const float* gamma_p = (const float*)d_in[25];
    const float* out_w   = (const float*)d_in[26];
    const float* out_b   = (const float*)d_in[27];
    const float* out_g   = (const float*)d_in[28];
    const float* out_bb  = (const float*)d_in[29];
    const float* out_m   = (const float*)d_in[30];
    const float* out_v   = (const float*)d_in[31];

    k_proj_all    <<<416, 256>>>(inp, featb, featc, featd,
                                 Wfa_all, Wfb_all, Wfc_all, Wfd_all,
                                 Wfa, Wfb, Wfc, Wfd);
    k_rowstats_all<<<1664, dim3(16,8)>>>();
    k_attn_all    <<<1664, dim3(16,8)>>>();
    k_fuse_all    <<<416, 256>>>(inp, fuse_w, fuse_b, fuse_g, fuse_bb, fuse_m, fuse_v, gamma_a,
                                 fuseP_w, fuseP_b, fuseP_g, fuseP_bb, fuseP_m, fuseP_v, gamma_p);
    k_combine     <<<(B_*CC*N_G)/256, 256>>>();
    k_conv        <<<dim3(16, B_), 256>>>(out_w, out_b, out_g, out_bb, out_m, out_v,
                                          (float*)d_out);
}